// round 12
// baseline (speedup 1.0000x reference)
#include <cuda_runtime.h>

#define B_ 64
#define N_ 1024
#define M_ 1024
#define Q_ 256          // float4 quads per row
#define QH 128          // quads per half-row
#define EPSF 1e-4f
#define NT 128          // 4 warps = 2 pairs
#define RG 8            // rows per item
#define NG 128          // N_/RG
#define UH 4            // quads per lane per half

__device__ float g_part[(size_t)B_ * NG * M_];
__device__ float g_c[B_ * M_];
__device__ unsigned g_ctr[8];
__device__ unsigned g_arrive;
__device__ volatile unsigned g_release;

__device__ __forceinline__ void grid_sync(unsigned nb) {
    __syncthreads();
    if (threadIdx.x == 0) {
        __threadfence();
        unsigned gen = g_release;
        __threadfence();
        if (atomicAdd(&g_arrive, 1) == nb - 1) {
            g_arrive = 0;
            __threadfence();
            g_release = gen + 1;
        } else {
            while (g_release == gen) __nanosleep(64);
        }
    }
    __syncthreads();
}

__device__ __forceinline__ float warp_sum(float v) {
#pragma unroll
    for (int o = 16; o; o >>= 1) v += __shfl_xor_sync(0xffffffffu, v, o);
    return v;
}
__device__ __forceinline__ void warp_sum2(float& a, float& b) {
#pragma unroll
    for (int o = 16; o; o >>= 1) {
        a += __shfl_xor_sync(0xffffffffu, a, o);
        b += __shfl_xor_sync(0xffffffffu, b, o);
    }
}

// pair barrier: warps {0,1} -> id 1, warps {2,3} -> id 2
#define BARP(p) asm volatile("bar.sync %0, 64;" :: "r"(1 + (p)) : "memory")

struct Shm {
    int sb[B_];          // batches sorted by nc descending (LPT)
    int vpre[B_ + 1];    // prefix of valid row-groups over sorted order
    int snr[B_], snc[B_];
    int idx[2];          // per-pair stolen item
    float cs[2][2];      // per-pair csum halves
    float xch[2][2][2][2];  // [pair][buf][half][rowInChunk]
};

// ---------------------------------------------------------------------------
// finalize: c_j = 1/(sum of group partials) masked; skips j>=nc reads.
// ---------------------------------------------------------------------------
__device__ void finalize_phase(const int* snr, const int* snc,
                               int gtid, int gthreads, int first) {
    for (int t = gtid; t < B_ * M_; t += gthreads) {
        int b = t >> 10, j = t & (M_ - 1);
        int nc = snc[b];
        if (j >= nc) { __stcg(&g_c[t], 0.f); continue; }
        int G = first ? NG : min(NG, (snr[b] + RG - 1) / RG);
        const float* pp = g_part + (size_t)b * NG * M_ + j;
        float a0 = 0.f, a1 = 0.f, a2 = 0.f, a3 = 0.f;
        int g = 0;
        for (; g + 4 <= G; g += 4) {
            a0 += __ldcg(pp + (size_t)(g + 0) * M_);
            a1 += __ldcg(pp + (size_t)(g + 1) * M_);
            a2 += __ldcg(pp + (size_t)(g + 2) * M_);
            a3 += __ldcg(pp + (size_t)(g + 3) * M_);
        }
        for (; g < G; g++) a0 += __ldcg(pp + (size_t)g * M_);
        float sum = ((a0 + a1) + (a2 + a3)) + (first ? (float)N_ * EPSF : 0.f);
        __stcg(&g_c[t], sum > 0.f ? __fdividef(1.f, sum) : 0.f);
    }
}

// ---------------------------------------------------------------------------
// Fused row+col pass: pair-cooperative item = (batch, 8 rows), each warp
// owns a column half. Row sums exchanged via double-buffered smem + BARP.
// eps folded: rowsum = dot(v,c) + e*csum ; acc = sum v*rinv + e*sum(rinv).
// Valid-region loads use default policy -> should be L2 hits after phase0.
// ---------------------------------------------------------------------------
__device__ void fused_pass(const float4* __restrict__ s4, Shm* sh,
                           unsigned* ctr, int lane, int pair, int half) {
    const int count = sh->vpre[B_];
    const int qoff = half * QH;
    for (;;) {
        if ((threadIdx.x & 63) == 0) sh->idx[pair] = (int)atomicAdd(ctr, 1u);
        BARP(pair);
        int idx = sh->idx[pair];
        BARP(pair);
        if (idx >= count) break;
        int lo = 0, hi = B_;
        while (hi - lo > 1) {
            int mid = (lo + hi) >> 1;
            if (sh->vpre[mid] <= idx) lo = mid; else hi = mid;
        }
        int b = sh->sb[lo], rg = idx - sh->vpre[lo];
        int nr = sh->snr[b], nc = sh->snc[b];
        int nq = (nc + 3) >> 2;
        int i0 = rg * RG, rows = min(RG, nr - i0);
        const float4* cp = reinterpret_cast<const float4*>(g_c) + b * Q_ + qoff;
        float4 c[UH], acc[UH];
        float csl = 0.f;
#pragma unroll
        for (int u = 0; u < UH; u++) {
            c[u] = make_float4(0.f, 0.f, 0.f, 0.f);
            if (qoff + lane + 32 * u < nq) c[u] = __ldcg(cp + lane + 32 * u);
            acc[u] = make_float4(0.f, 0.f, 0.f, 0.f);
            csl += (c[u].x + c[u].y) + (c[u].z + c[u].w);
        }
        csl = warp_sum(csl);
        if (lane == 0) sh->cs[pair][half] = csl;
        BARP(pair);
        float ecs = EPSF * (sh->cs[pair][0] + sh->cs[pair][1]);
        const float4* sp = s4 + (size_t)(b * N_ + i0) * Q_ + qoff;
        float rsum = 0.f;
        int r = 0;
        for (; r + 2 <= rows; r += 2) {
            int buf = (r >> 1) & 1;
            float4 v0[UH], v1[UH];
            float rs0 = 0.f, rs1 = 0.f;
#pragma unroll
            for (int u = 0; u < UH; u++) {
                v0[u] = make_float4(0.f, 0.f, 0.f, 0.f);
                v1[u] = v0[u];
                if (qoff + lane + 32 * u < nq) {
                    v0[u] = __ldg(sp + r * Q_ + lane + 32 * u);
                    v1[u] = __ldg(sp + (r + 1) * Q_ + lane + 32 * u);
                }
                rs0 += (v0[u].x * c[u].x + v0[u].y * c[u].y) +
                       (v0[u].z * c[u].z + v0[u].w * c[u].w);
                rs1 += (v1[u].x * c[u].x + v1[u].y * c[u].y) +
                       (v1[u].z * c[u].z + v1[u].w * c[u].w);
            }
            warp_sum2(rs0, rs1);
            if (lane == 0) {
                sh->xch[pair][buf][half][0] = rs0;
                sh->xch[pair][buf][half][1] = rs1;
            }
            BARP(pair);
            float t0 = sh->xch[pair][buf][0][0] + sh->xch[pair][buf][1][0] + ecs;
            float t1 = sh->xch[pair][buf][0][1] + sh->xch[pair][buf][1][1] + ecs;
            float ri0 = t0 > 0.f ? __fdividef(1.f, t0) : 0.f;
            float ri1 = t1 > 0.f ? __fdividef(1.f, t1) : 0.f;
            rsum += ri0 + ri1;
#pragma unroll
            for (int u = 0; u < UH; u++) {
                acc[u].x += v0[u].x * ri0 + v1[u].x * ri1;
                acc[u].y += v0[u].y * ri0 + v1[u].y * ri1;
                acc[u].z += v0[u].z * ri0 + v1[u].z * ri1;
                acc[u].w += v0[u].w * ri0 + v1[u].w * ri1;
            }
        }
        if (r < rows) {
            int buf = (r >> 1) & 1;
            float4 v0[UH];
            float rs0 = 0.f;
#pragma unroll
            for (int u = 0; u < UH; u++) {
                v0[u] = make_float4(0.f, 0.f, 0.f, 0.f);
                if (qoff + lane + 32 * u < nq)
                    v0[u] = __ldg(sp + r * Q_ + lane + 32 * u);
                rs0 += (v0[u].x * c[u].x + v0[u].y * c[u].y) +
                       (v0[u].z * c[u].z + v0[u].w * c[u].w);
            }
            rs0 = warp_sum(rs0);
            if (lane == 0) sh->xch[pair][buf][half][0] = rs0;
            BARP(pair);
            float t0 = sh->xch[pair][buf][0][0] + sh->xch[pair][buf][1][0] + ecs;
            float ri0 = t0 > 0.f ? __fdividef(1.f, t0) : 0.f;
            rsum += ri0;
#pragma unroll
            for (int u = 0; u < UH; u++) {
                acc[u].x += v0[u].x * ri0; acc[u].y += v0[u].y * ri0;
                acc[u].z += v0[u].z * ri0; acc[u].w += v0[u].w * ri0;
            }
        }
        float er = EPSF * rsum;
        float4* pp = reinterpret_cast<float4*>(g_part) +
                     (size_t)(b * NG + rg) * Q_ + qoff;
#pragma unroll
        for (int u = 0; u < UH; u++) {
            if (qoff + lane + 32 * u < nq) {
                float4 o;
                o.x = acc[u].x + er; o.y = acc[u].y + er;
                o.z = acc[u].z + er; o.w = acc[u].w + er;
                __stcg(pp + lane + 32 * u, o);
            }
        }
    }
}

// ---------------------------------------------------------------------------
// Final: iter-9 row norm + masked output. Pair-cooperative, work-stolen.
// s reads should hit L2 (valid region kept resident); output streamed.
// ---------------------------------------------------------------------------
__device__ void final_pass(const float4* __restrict__ s4,
                           float4* __restrict__ o4, Shm* sh,
                           int lane, int pair, int half) {
    const int total = B_ * NG;
    const int qoff = half * QH;
    const float4 z = make_float4(0.f, 0.f, 0.f, 0.f);
    for (;;) {
        if ((threadIdx.x & 63) == 0) sh->idx[pair] = (int)atomicAdd(&g_ctr[5], 1u);
        BARP(pair);
        int idx = sh->idx[pair];
        BARP(pair);
        if (idx >= total) break;
        int b = idx >> 7, rg = idx & (NG - 1);
        int nr = sh->snr[b];
        int i0 = rg * RG;
        float4* op = o4 + (size_t)(b * N_ + i0) * Q_ + qoff;
        if (i0 >= nr) {
            for (int r = 0; r < RG; r++)
#pragma unroll
                for (int u = 0; u < UH; u++)
                    __stcs(op + r * Q_ + lane + 32 * u, z);
            continue;
        }
        int nc = sh->snc[b];
        int nq = (nc + 3) >> 2;
        int rows = min(RG, nr - i0);
        const float4* cp = reinterpret_cast<const float4*>(g_c) + b * Q_ + qoff;
        float4 c[UH];
        float csl = 0.f;
#pragma unroll
        for (int u = 0; u < UH; u++) {
            c[u] = z;
            if (qoff + lane + 32 * u < nq) c[u] = __ldcg(cp + lane + 32 * u);
            csl += (c[u].x + c[u].y) + (c[u].z + c[u].w);
        }
        csl = warp_sum(csl);
        if (lane == 0) sh->cs[pair][half] = csl;
        BARP(pair);
        float ecs = EPSF * (sh->cs[pair][0] + sh->cs[pair][1]);
        const float4* sp = s4 + (size_t)(b * N_ + i0) * Q_ + qoff;
        int r = 0;
        for (; r + 2 <= rows; r += 2) {
            int buf = (r >> 1) & 1;
            float4 v0[UH], v1[UH];
            float rs0 = 0.f, rs1 = 0.f;
#pragma unroll
            for (int u = 0; u < UH; u++) {
                v0[u] = z; v1[u] = z;
                if (qoff + lane + 32 * u < nq) {
                    v0[u] = __ldg(sp + r * Q_ + lane + 32 * u);
                    v1[u] = __ldg(sp + (r + 1) * Q_ + lane + 32 * u);
                }
                rs0 += (v0[u].x * c[u].x + v0[u].y * c[u].y) +
                       (v0[u].z * c[u].z + v0[u].w * c[u].w);
                rs1 += (v1[u].x * c[u].x + v1[u].y * c[u].y) +
                       (v1[u].z * c[u].z + v1[u].w * c[u].w);
            }
            warp_sum2(rs0, rs1);
            if (lane == 0) {
                sh->xch[pair][buf][half][0] = rs0;
                sh->xch[pair][buf][half][1] = rs1;
            }
            BARP(pair);
            float t0 = sh->xch[pair][buf][0][0] + sh->xch[pair][buf][1][0] + ecs;
            float t1 = sh->xch[pair][buf][0][1] + sh->xch[pair][buf][1][1] + ecs;
            float ri0 = t0 > 0.f ? __fdividef(1.f, t0) : 0.f;
            float ri1 = t1 > 0.f ? __fdividef(1.f, t1) : 0.f;
#pragma unroll
            for (int u = 0; u < UH; u++) {
                float4 o0, o1;
                o0.x = (v0[u].x + EPSF) * ri0 * c[u].x;  // c==0 past nc -> 0
                o0.y = (v0[u].y + EPSF) * ri0 * c[u].y;
                o0.z = (v0[u].z + EPSF) * ri0 * c[u].z;
                o0.w = (v0[u].w + EPSF) * ri0 * c[u].w;
                o1.x = (v1[u].x + EPSF) * ri1 * c[u].x;
                o1.y = (v1[u].y + EPSF) * ri1 * c[u].y;
                o1.z = (v1[u].z + EPSF) * ri1 * c[u].z;
                o1.w = (v1[u].w + EPSF) * ri1 * c[u].w;
                __stcs(op + r * Q_ + lane + 32 * u, o0);
                __stcs(op + (r + 1) * Q_ + lane + 32 * u, o1);
            }
        }
        if (r < rows) {
            int buf = (r >> 1) & 1;
            float4 v0[UH];
            float rs0 = 0.f;
#pragma unroll
            for (int u = 0; u < UH; u++) {
                v0[u] = z;
                if (qoff + lane + 32 * u < nq)
                    v0[u] = __ldg(sp + r * Q_ + lane + 32 * u);
                rs0 += (v0[u].x * c[u].x + v0[u].y * c[u].y) +
                       (v0[u].z * c[u].z + v0[u].w * c[u].w);
            }
            rs0 = warp_sum(rs0);
            if (lane == 0) sh->xch[pair][buf][half][0] = rs0;
            BARP(pair);
            float t0 = sh->xch[pair][buf][0][0] + sh->xch[pair][buf][1][0] + ecs;
            float ri0 = t0 > 0.f ? __fdividef(1.f, t0) : 0.f;
#pragma unroll
            for (int u = 0; u < UH; u++) {
                float4 o0;
                o0.x = (v0[u].x + EPSF) * ri0 * c[u].x;
                o0.y = (v0[u].y + EPSF) * ri0 * c[u].y;
                o0.z = (v0[u].z + EPSF) * ri0 * c[u].z;
                o0.w = (v0[u].w + EPSF) * ri0 * c[u].w;
                __stcs(op + r * Q_ + lane + 32 * u, o0);
            }
        }
        for (int rr = rows; rr < RG; rr++)
#pragma unroll
            for (int u = 0; u < UH; u++)
                __stcs(op + rr * Q_ + lane + 32 * u, z);
    }
}

// ---------------------------------------------------------------------------
__global__ void __launch_bounds__(NT, 5)
sinkhorn_kernel(const float* __restrict__ s, const int* __restrict__ nrows,
                const int* __restrict__ ncols, float* __restrict__ out) {
    __shared__ Shm shm;
    const int tid = threadIdx.x;
    const int lane = tid & 31;
    const int pair = tid >> 6;
    const int half = (tid >> 5) & 1;
    const unsigned nb = gridDim.x;

    if (tid < B_) {
        shm.snr[tid] = __ldg(nrows + tid);
        shm.snc[tid] = __ldg(ncols + tid);
    }
    __syncthreads();
    if (tid < B_) {                      // parallel rank sort by nc desc (LPT)
        int myc = shm.snc[tid];
        int rank = 0;
        for (int j = 0; j < B_; j++) {
            int cj = shm.snc[j];
            rank += (cj > myc) || (cj == myc && j < tid);
        }
        shm.sb[rank] = tid;
    }
    __syncthreads();
    if (tid <= B_) {                     // prefix of valid groups, sorted order
        int a = 0;
        for (int k = 0; k < tid; k++)
            a += (shm.snr[shm.sb[k]] + RG - 1) / RG;
        shm.vpre[tid] = a;
    }
    __syncthreads();

    const float4* s4 = reinterpret_cast<const float4*>(s);
    float4* o4 = reinterpret_cast<float4*>(out);
    const int gtid = blockIdx.x * NT + tid;
    const int gthreads = nb * NT;

    // ---- phase 0: iter-0 column partials (all rows, valid cols) ----
    // Dead rows (i >= nr) are single-use: stream them (__ldcs) so the valid
    // region — reused by 4 fused passes + final — stays L2-resident.
    for (;;) {
        unsigned sv = 0;
        if (lane == 0) sv = atomicAdd(&g_ctr[0], 1u);
        int item = (int)__shfl_sync(0xffffffffu, sv, 0);
        if (item >= B_ * NG * 2) break;
        int b = shm.sb[item >> 8];
        int rem = item & 255;
        int rg = rem >> 1, hf = rem & 1;
        int nr = shm.snr[b];
        int nq = (shm.snc[b] + 3) >> 2;
        int qoff = hf * QH;
        if (qoff >= nq) continue;
        const float4* sp = s4 + (size_t)(b * N_ + rg * RG) * Q_ + qoff;
        float4 acc[UH];
#pragma unroll
        for (int u = 0; u < UH; u++) acc[u] = make_float4(0.f, 0.f, 0.f, 0.f);
        for (int r = 0; r < RG; r++) {
            bool live = (rg * RG + r) < nr;   // reused later?
#pragma unroll
            for (int u = 0; u < UH; u++) {
                if (qoff + lane + 32 * u < nq) {
                    float4 v = live ? __ldg(sp + r * Q_ + lane + 32 * u)
                                    : __ldcs(sp + r * Q_ + lane + 32 * u);
                    acc[u].x += v.x; acc[u].y += v.y;
                    acc[u].z += v.z; acc[u].w += v.w;
                }
            }
        }
        float4* pp = reinterpret_cast<float4*>(g_part) +
                     (size_t)(b * NG + rg) * Q_ + qoff;
#pragma unroll
        for (int u = 0; u < UH; u++)
            if (qoff + lane + 32 * u < nq) __stcg(pp + lane + 32 * u, acc[u]);
    }
    grid_sync(nb);

    finalize_phase(shm.snr, shm.snc, gtid, gthreads, 1);
    // safe reset: phase0 ctr done; fused/final ctrs unused until after sync
    if (blockIdx.x == 0 && tid < 8) g_ctr[tid] = 0;
    grid_sync(nb);

#pragma unroll 1
    for (int k = 0; k < 4; k++) {        // iters 1..8
        fused_pass(s4, &shm, &g_ctr[1 + k], lane, pair, half);
        grid_sync(nb);
        finalize_phase(shm.snr, shm.snc, gtid, gthreads, 0);
        grid_sync(nb);
    }

    final_pass(s4, o4, &shm, lane, pair, half);  // iter 9 + output
}

extern "C" void kernel_launch(void* const* d_in, const int* in_sizes, int n_in,
                              void* d_out, int out_size) {
    const float* s   = (const float*)d_in[0];
    const int* nrows = (const int*)d_in[1];
    const int* ncols = (const int*)d_in[2];
    float* out       = (float*)d_out;

    int dev = 0;
    cudaGetDevice(&dev);
    int sms = 0;
    cudaDeviceGetAttribute(&sms, cudaDevAttrMultiProcessorCount, dev);
    int bpm = 0;
    cudaOccupancyMaxActiveBlocksPerMultiprocessor(&bpm, sinkhorn_kernel, NT, 0);
    int grid = sms * bpm;
    if (grid < 1) grid = 1;

    sinkhorn_kernel<<<grid, NT>>>(s, nrows, ncols, out);
}

// round 13
// speedup vs baseline: 1.2101x; 1.2101x over previous
#include <cuda_runtime.h>

#define B_ 64
#define N_ 1024
#define M_ 1024
#define Q_ 256          // float4 quads per row
#define QH 128          // quads per half-row
#define EPSF 1e-4f
#define NT 128          // 4 warps = 2 pairs
#define RG 8            // rows per item
#define NG 128          // N_/RG
#define UH 4            // quads per lane per half

__device__ float g_part[(size_t)B_ * NG * M_];
__device__ float g_c[B_ * M_];
__device__ unsigned g_ctr[8];
__device__ unsigned g_arrive;
__device__ volatile unsigned g_release;

__device__ __forceinline__ void grid_sync(unsigned nb) {
    __syncthreads();
    if (threadIdx.x == 0) {
        __threadfence();
        unsigned gen = g_release;
        __threadfence();
        if (atomicAdd(&g_arrive, 1) == nb - 1) {
            g_arrive = 0;
            __threadfence();
            g_release = gen + 1;
        } else {
            while (g_release == gen) __nanosleep(64);
        }
    }
    __syncthreads();
}

__device__ __forceinline__ float warp_sum(float v) {
#pragma unroll
    for (int o = 16; o; o >>= 1) v += __shfl_xor_sync(0xffffffffu, v, o);
    return v;
}
__device__ __forceinline__ void warp_sum2(float& a, float& b) {
#pragma unroll
    for (int o = 16; o; o >>= 1) {
        a += __shfl_xor_sync(0xffffffffu, a, o);
        b += __shfl_xor_sync(0xffffffffu, b, o);
    }
}

// pair barrier: warps {0,1} -> id 1, warps {2,3} -> id 2
#define BARP(p) asm volatile("bar.sync %0, 64;" :: "r"(1 + (p)) : "memory")

struct Shm {
    int sb[B_];          // batches sorted by nc descending (LPT)
    int vpre[B_ + 1];    // prefix of valid row-groups over sorted order
    int snr[B_], snc[B_];
    int idx[2];          // per-pair stolen item
    float cs[2][2];      // per-pair csum halves
    float xch[2][2][2][2];  // [pair][buf][half][rowInChunk]
};

// ---------------------------------------------------------------------------
// finalize: c_j = 1/(sum of group partials) masked; skips j>=nc reads.
// ---------------------------------------------------------------------------
__device__ void finalize_phase(const int* snr, const int* snc,
                               int gtid, int gthreads, int first) {
    for (int t = gtid; t < B_ * M_; t += gthreads) {
        int b = t >> 10, j = t & (M_ - 1);
        int nc = snc[b];
        if (j >= nc) { __stcg(&g_c[t], 0.f); continue; }
        int G = first ? NG : min(NG, (snr[b] + RG - 1) / RG);
        const float* pp = g_part + (size_t)b * NG * M_ + j;
        float a0 = 0.f, a1 = 0.f, a2 = 0.f, a3 = 0.f;
        int g = 0;
        for (; g + 4 <= G; g += 4) {
            a0 += __ldcg(pp + (size_t)(g + 0) * M_);
            a1 += __ldcg(pp + (size_t)(g + 1) * M_);
            a2 += __ldcg(pp + (size_t)(g + 2) * M_);
            a3 += __ldcg(pp + (size_t)(g + 3) * M_);
        }
        for (; g < G; g++) a0 += __ldcg(pp + (size_t)g * M_);
        float sum = ((a0 + a1) + (a2 + a3)) + (first ? (float)N_ * EPSF : 0.f);
        __stcg(&g_c[t], sum > 0.f ? __fdividef(1.f, sum) : 0.f);
    }
}

// ---------------------------------------------------------------------------
// Fused row+col pass: pair-cooperative item = (batch, 8 rows), each warp
// owns a column half. Row sums exchanged via double-buffered smem + BARP.
// eps folded: rowsum = dot(v,c) + e*csum ; acc = sum v*rinv + e*sum(rinv).
// ---------------------------------------------------------------------------
__device__ void fused_pass(const float4* __restrict__ s4, Shm* sh,
                           unsigned* ctr, int lane, int pair, int half) {
    const int count = sh->vpre[B_];
    const int qoff = half * QH;
    for (;;) {
        if ((threadIdx.x & 63) == 0) sh->idx[pair] = (int)atomicAdd(ctr, 1u);
        BARP(pair);
        int idx = sh->idx[pair];
        BARP(pair);
        if (idx >= count) break;
        int lo = 0, hi = B_;
        while (hi - lo > 1) {
            int mid = (lo + hi) >> 1;
            if (sh->vpre[mid] <= idx) lo = mid; else hi = mid;
        }
        int b = sh->sb[lo], rg = idx - sh->vpre[lo];
        int nr = sh->snr[b], nc = sh->snc[b];
        int nq = (nc + 3) >> 2;
        int i0 = rg * RG, rows = min(RG, nr - i0);
        const float4* cp = reinterpret_cast<const float4*>(g_c) + b * Q_ + qoff;
        float4 c[UH], acc[UH];
        float csl = 0.f;
#pragma unroll
        for (int u = 0; u < UH; u++) {
            c[u] = make_float4(0.f, 0.f, 0.f, 0.f);
            if (qoff + lane + 32 * u < nq) c[u] = __ldcg(cp + lane + 32 * u);
            acc[u] = make_float4(0.f, 0.f, 0.f, 0.f);
            csl += (c[u].x + c[u].y) + (c[u].z + c[u].w);
        }
        csl = warp_sum(csl);
        if (lane == 0) sh->cs[pair][half] = csl;
        BARP(pair);
        float ecs = EPSF * (sh->cs[pair][0] + sh->cs[pair][1]);
        const float4* sp = s4 + (size_t)(b * N_ + i0) * Q_ + qoff;
        float rsum = 0.f;
        int r = 0;
        for (; r + 2 <= rows; r += 2) {
            int buf = (r >> 1) & 1;
            float4 v0[UH], v1[UH];
            float rs0 = 0.f, rs1 = 0.f;
#pragma unroll
            for (int u = 0; u < UH; u++) {
                v0[u] = make_float4(0.f, 0.f, 0.f, 0.f);
                v1[u] = v0[u];
                if (qoff + lane + 32 * u < nq) {
                    v0[u] = __ldg(sp + r * Q_ + lane + 32 * u);
                    v1[u] = __ldg(sp + (r + 1) * Q_ + lane + 32 * u);
                }
                rs0 += (v0[u].x * c[u].x + v0[u].y * c[u].y) +
                       (v0[u].z * c[u].z + v0[u].w * c[u].w);
                rs1 += (v1[u].x * c[u].x + v1[u].y * c[u].y) +
                       (v1[u].z * c[u].z + v1[u].w * c[u].w);
            }
            warp_sum2(rs0, rs1);
            if (lane == 0) {
                sh->xch[pair][buf][half][0] = rs0;
                sh->xch[pair][buf][half][1] = rs1;
            }
            BARP(pair);
            float t0 = sh->xch[pair][buf][0][0] + sh->xch[pair][buf][1][0] + ecs;
            float t1 = sh->xch[pair][buf][0][1] + sh->xch[pair][buf][1][1] + ecs;
            float ri0 = t0 > 0.f ? __fdividef(1.f, t0) : 0.f;
            float ri1 = t1 > 0.f ? __fdividef(1.f, t1) : 0.f;
            rsum += ri0 + ri1;
#pragma unroll
            for (int u = 0; u < UH; u++) {
                acc[u].x += v0[u].x * ri0 + v1[u].x * ri1;
                acc[u].y += v0[u].y * ri0 + v1[u].y * ri1;
                acc[u].z += v0[u].z * ri0 + v1[u].z * ri1;
                acc[u].w += v0[u].w * ri0 + v1[u].w * ri1;
            }
        }
        if (r < rows) {
            int buf = (r >> 1) & 1;
            float4 v0[UH];
            float rs0 = 0.f;
#pragma unroll
            for (int u = 0; u < UH; u++) {
                v0[u] = make_float4(0.f, 0.f, 0.f, 0.f);
                if (qoff + lane + 32 * u < nq)
                    v0[u] = __ldg(sp + r * Q_ + lane + 32 * u);
                rs0 += (v0[u].x * c[u].x + v0[u].y * c[u].y) +
                       (v0[u].z * c[u].z + v0[u].w * c[u].w);
            }
            rs0 = warp_sum(rs0);
            if (lane == 0) sh->xch[pair][buf][half][0] = rs0;
            BARP(pair);
            float t0 = sh->xch[pair][buf][0][0] + sh->xch[pair][buf][1][0] + ecs;
            float ri0 = t0 > 0.f ? __fdividef(1.f, t0) : 0.f;
            rsum += ri0;
#pragma unroll
            for (int u = 0; u < UH; u++) {
                acc[u].x += v0[u].x * ri0; acc[u].y += v0[u].y * ri0;
                acc[u].z += v0[u].z * ri0; acc[u].w += v0[u].w * ri0;
            }
        }
        float er = EPSF * rsum;
        float4* pp = reinterpret_cast<float4*>(g_part) +
                     (size_t)(b * NG + rg) * Q_ + qoff;
#pragma unroll
        for (int u = 0; u < UH; u++) {
            if (qoff + lane + 32 * u < nq) {
                float4 o;
                o.x = acc[u].x + er; o.y = acc[u].y + er;
                o.z = acc[u].z + er; o.w = acc[u].w + er;
                __stcg(pp + lane + 32 * u, o);
            }
        }
    }
}

// ---------------------------------------------------------------------------
// Final: iter-9 row norm + masked output. Pair-cooperative, work-stolen.
// ---------------------------------------------------------------------------
__device__ void final_pass(const float4* __restrict__ s4,
                           float4* __restrict__ o4, Shm* sh,
                           int lane, int pair, int half) {
    const int total = B_ * NG;
    const int qoff = half * QH;
    const float4 z = make_float4(0.f, 0.f, 0.f, 0.f);
    for (;;) {
        if ((threadIdx.x & 63) == 0) sh->idx[pair] = (int)atomicAdd(&g_ctr[5], 1u);
        BARP(pair);
        int idx = sh->idx[pair];
        BARP(pair);
        if (idx >= total) break;
        int b = idx >> 7, rg = idx & (NG - 1);
        int nr = sh->snr[b];
        int i0 = rg * RG;
        float4* op = o4 + (size_t)(b * N_ + i0) * Q_ + qoff;
        if (i0 >= nr) {
            for (int r = 0; r < RG; r++)
#pragma unroll
                for (int u = 0; u < UH; u++)
                    __stcs(op + r * Q_ + lane + 32 * u, z);
            continue;
        }
        int nc = sh->snc[b];
        int nq = (nc + 3) >> 2;
        int rows = min(RG, nr - i0);
        const float4* cp = reinterpret_cast<const float4*>(g_c) + b * Q_ + qoff;
        float4 c[UH];
        float csl = 0.f;
#pragma unroll
        for (int u = 0; u < UH; u++) {
            c[u] = z;
            if (qoff + lane + 32 * u < nq) c[u] = __ldcg(cp + lane + 32 * u);
            csl += (c[u].x + c[u].y) + (c[u].z + c[u].w);
        }
        csl = warp_sum(csl);
        if (lane == 0) sh->cs[pair][half] = csl;
        BARP(pair);
        float ecs = EPSF * (sh->cs[pair][0] + sh->cs[pair][1]);
        const float4* sp = s4 + (size_t)(b * N_ + i0) * Q_ + qoff;
        int r = 0;
        for (; r + 2 <= rows; r += 2) {
            int buf = (r >> 1) & 1;
            float4 v0[UH], v1[UH];
            float rs0 = 0.f, rs1 = 0.f;
#pragma unroll
            for (int u = 0; u < UH; u++) {
                v0[u] = z; v1[u] = z;
                if (qoff + lane + 32 * u < nq) {
                    v0[u] = __ldg(sp + r * Q_ + lane + 32 * u);
                    v1[u] = __ldg(sp + (r + 1) * Q_ + lane + 32 * u);
                }
                rs0 += (v0[u].x * c[u].x + v0[u].y * c[u].y) +
                       (v0[u].z * c[u].z + v0[u].w * c[u].w);
                rs1 += (v1[u].x * c[u].x + v1[u].y * c[u].y) +
                       (v1[u].z * c[u].z + v1[u].w * c[u].w);
            }
            warp_sum2(rs0, rs1);
            if (lane == 0) {
                sh->xch[pair][buf][half][0] = rs0;
                sh->xch[pair][buf][half][1] = rs1;
            }
            BARP(pair);
            float t0 = sh->xch[pair][buf][0][0] + sh->xch[pair][buf][1][0] + ecs;
            float t1 = sh->xch[pair][buf][0][1] + sh->xch[pair][buf][1][1] + ecs;
            float ri0 = t0 > 0.f ? __fdividef(1.f, t0) : 0.f;
            float ri1 = t1 > 0.f ? __fdividef(1.f, t1) : 0.f;
#pragma unroll
            for (int u = 0; u < UH; u++) {
                float4 o0, o1;
                o0.x = (v0[u].x + EPSF) * ri0 * c[u].x;  // c==0 past nc -> 0
                o0.y = (v0[u].y + EPSF) * ri0 * c[u].y;
                o0.z = (v0[u].z + EPSF) * ri0 * c[u].z;
                o0.w = (v0[u].w + EPSF) * ri0 * c[u].w;
                o1.x = (v1[u].x + EPSF) * ri1 * c[u].x;
                o1.y = (v1[u].y + EPSF) * ri1 * c[u].y;
                o1.z = (v1[u].z + EPSF) * ri1 * c[u].z;
                o1.w = (v1[u].w + EPSF) * ri1 * c[u].w;
                __stcs(op + r * Q_ + lane + 32 * u, o0);
                __stcs(op + (r + 1) * Q_ + lane + 32 * u, o1);
            }
        }
        if (r < rows) {
            int buf = (r >> 1) & 1;
            float4 v0[UH];
            float rs0 = 0.f;
#pragma unroll
            for (int u = 0; u < UH; u++) {
                v0[u] = z;
                if (qoff + lane + 32 * u < nq)
                    v0[u] = __ldg(sp + r * Q_ + lane + 32 * u);
                rs0 += (v0[u].x * c[u].x + v0[u].y * c[u].y) +
                       (v0[u].z * c[u].z + v0[u].w * c[u].w);
            }
            rs0 = warp_sum(rs0);
            if (lane == 0) sh->xch[pair][buf][half][0] = rs0;
            BARP(pair);
            float t0 = sh->xch[pair][buf][0][0] + sh->xch[pair][buf][1][0] + ecs;
            float ri0 = t0 > 0.f ? __fdividef(1.f, t0) : 0.f;
#pragma unroll
            for (int u = 0; u < UH; u++) {
                float4 o0;
                o0.x = (v0[u].x + EPSF) * ri0 * c[u].x;
                o0.y = (v0[u].y + EPSF) * ri0 * c[u].y;
                o0.z = (v0[u].z + EPSF) * ri0 * c[u].z;
                o0.w = (v0[u].w + EPSF) * ri0 * c[u].w;
                __stcs(op + r * Q_ + lane + 32 * u, o0);
            }
        }
        for (int rr = rows; rr < RG; rr++)
#pragma unroll
            for (int u = 0; u < UH; u++)
                __stcs(op + rr * Q_ + lane + 32 * u, z);
    }
}

// ---------------------------------------------------------------------------
__global__ void __launch_bounds__(NT, 5)
sinkhorn_kernel(const float* __restrict__ s, const int* __restrict__ nrows,
                const int* __restrict__ ncols, float* __restrict__ out) {
    __shared__ Shm shm;
    const int tid = threadIdx.x;
    const int lane = tid & 31;
    const int pair = tid >> 6;
    const int half = (tid >> 5) & 1;
    const unsigned nb = gridDim.x;

    if (tid < B_) {
        shm.snr[tid] = __ldg(nrows + tid);
        shm.snc[tid] = __ldg(ncols + tid);
    }
    __syncthreads();
    if (tid < B_) {                      // parallel rank sort by nc desc (LPT)
        int myc = shm.snc[tid];
        int rank = 0;
        for (int j = 0; j < B_; j++) {
            int cj = shm.snc[j];
            rank += (cj > myc) || (cj == myc && j < tid);
        }
        shm.sb[rank] = tid;
    }
    __syncthreads();
    if (tid <= B_) {                     // prefix of valid groups, sorted order
        int a = 0;
        for (int k = 0; k < tid; k++)
            a += (shm.snr[shm.sb[k]] + RG - 1) / RG;
        shm.vpre[tid] = a;
    }
    __syncthreads();

    const float4* s4 = reinterpret_cast<const float4*>(s);
    float4* o4 = reinterpret_cast<float4*>(out);
    const int gtid = blockIdx.x * NT + tid;
    const int gthreads = nb * NT;

    // ---- phase 0: iter-0 column partials (all rows, valid cols) ----
    // Live rows (reused by later passes): default-policy loads, paired for
    // MLP. Dead rows (single-use): identical paired loops but __ldcs, so
    // they stream through L2 without evicting the live region. The loop is
    // split at the live/dead boundary — no per-element policy branch.
    for (;;) {
        unsigned sv = 0;
        if (lane == 0) sv = atomicAdd(&g_ctr[0], 1u);
        int item = (int)__shfl_sync(0xffffffffu, sv, 0);
        if (item >= B_ * NG * 2) break;
        int b = shm.sb[item >> 8];
        int rem = item & 255;
        int rg = rem >> 1, hf = rem & 1;
        int nr = shm.snr[b];
        int nq = (shm.snc[b] + 3) >> 2;
        int qoff = hf * QH;
        if (qoff >= nq) continue;
        int i0 = rg * RG;
        int live = nr - i0;
        if (live < 0) live = 0;
        if (live > RG) live = RG;
        const float4* sp = s4 + (size_t)(b * N_ + i0) * Q_ + qoff;
        float4 acc[UH];
#pragma unroll
        for (int u = 0; u < UH; u++) acc[u] = make_float4(0.f, 0.f, 0.f, 0.f);
        int r = 0;
        for (; r + 2 <= live; r += 2) {       // live rows, paired, cached
#pragma unroll
            for (int u = 0; u < UH; u++) {
                if (qoff + lane + 32 * u < nq) {
                    float4 v0 = __ldg(sp + r * Q_ + lane + 32 * u);
                    float4 v1 = __ldg(sp + (r + 1) * Q_ + lane + 32 * u);
                    acc[u].x += v0.x + v1.x; acc[u].y += v0.y + v1.y;
                    acc[u].z += v0.z + v1.z; acc[u].w += v0.w + v1.w;
                }
            }
        }
        if (r < live) {                        // odd live tail, cached
#pragma unroll
            for (int u = 0; u < UH; u++) {
                if (qoff + lane + 32 * u < nq) {
                    float4 v0 = __ldg(sp + r * Q_ + lane + 32 * u);
                    acc[u].x += v0.x; acc[u].y += v0.y;
                    acc[u].z += v0.z; acc[u].w += v0.w;
                }
            }
            r++;
        }
        for (; r + 2 <= RG; r += 2) {          // dead rows, paired, streaming
#pragma unroll
            for (int u = 0; u < UH; u++) {
                if (qoff + lane + 32 * u < nq) {
                    float4 v0 = __ldcs(sp + r * Q_ + lane + 32 * u);
                    float4 v1 = __ldcs(sp + (r + 1) * Q_ + lane + 32 * u);
                    acc[u].x += v0.x + v1.x; acc[u].y += v0.y + v1.y;
                    acc[u].z += v0.z + v1.z; acc[u].w += v0.w + v1.w;
                }
            }
        }
        if (r < RG) {                          // odd dead tail, streaming
#pragma unroll
            for (int u = 0; u < UH; u++) {
                if (qoff + lane + 32 * u < nq) {
                    float4 v0 = __ldcs(sp + r * Q_ + lane + 32 * u);
                    acc[u].x += v0.x; acc[u].y += v0.y;
                    acc[u].z += v0.z; acc[u].w += v0.w;
                }
            }
        }
        float4* pp = reinterpret_cast<float4*>(g_part) +
                     (size_t)(b * NG + rg) * Q_ + qoff;
#pragma unroll
        for (int u = 0; u < UH; u++)
            if (qoff + lane + 32 * u < nq) __stcg(pp + lane + 32 * u, acc[u]);
    }
    grid_sync(nb);

    finalize_phase(shm.snr, shm.snc, gtid, gthreads, 1);
    // safe reset: phase0 ctr done; fused/final ctrs unused until after sync
    if (blockIdx.x == 0 && tid < 8) g_ctr[tid] = 0;
    grid_sync(nb);

#pragma unroll 1
    for (int k = 0; k < 4; k++) {        // iters 1..8
        fused_pass(s4, &shm, &g_ctr[1 + k], lane, pair, half);
        grid_sync(nb);
        finalize_phase(shm.snr, shm.snc, gtid, gthreads, 0);
        grid_sync(nb);
    }

    final_pass(s4, o4, &shm, lane, pair, half);  // iter 9 + output
}

extern "C" void kernel_launch(void* const* d_in, const int* in_sizes, int n_in,
                              void* d_out, int out_size) {
    const float* s   = (const float*)d_in[0];
    const int* nrows = (const int*)d_in[1];
    const int* ncols = (const int*)d_in[2];
    float* out       = (float*)d_out;

    int dev = 0;
    cudaGetDevice(&dev);
    int sms = 0;
    cudaDeviceGetAttribute(&sms, cudaDevAttrMultiProcessorCount, dev);
    int bpm = 0;
    cudaOccupancyMaxActiveBlocksPerMultiprocessor(&bpm, sinkhorn_kernel, NT, 0);
    int grid = sms * bpm;
    if (grid < 1) grid = 1;

    sinkhorn_kernel<<<grid, NT>>>(s, nrows, ncols, out);
}